// round 15
// baseline (speedup 1.0000x reference)
#include <cuda_runtime.h>
#include <cuda_bf16.h>
#include <cuda_fp16.h>
#include <cstdint>

#define BDIM 8
#define CDIM 1024
#define LDIM 1024
#define HDIM 16
#define DK   64
#define NH   (BDIM*HDIM)
#define SCALE 0.125f
#define L2E   1.44269504f
#define KPJ  1024
#define KH   64
#define P64  72              // pitch for 64-wide fp16 rows
#define P128 136             // pitch for 128-wide fp16 rows

// ---------------- scratch (device globals; no allocation allowed) ----------
static __device__ float g_rz[NH*LDIM];

static __device__ __half g_Wqp[CDIM*KPJ];
static __device__ __half g_Wkp[CDIM*KPJ];
static __device__ __half g_Wvp[CDIM*KPJ];
static __device__ __half g_Xqp[BDIM*CDIM*LDIM];  // [b][c][l] fp16
static __device__ __half g_Xkp[BDIM*CDIM*LDIM];
static __device__ __half g_Xvp[BDIM*CDIM*LDIM];

static __device__ __half g_qT[NH*DK*LDIM];       // [bh][c][t] * SCALE*log2e
static __device__ __half g_kT[NH*DK*LDIM];       // [bh][c][s]
static __device__ __half g_vA[NH*16*DK*KH];      // [bh][s>>6][c][sl]

// ---------------------------------------------------------------------------
// helpers
// ---------------------------------------------------------------------------
__device__ __forceinline__ void mma16816h(float c[4],
    uint32_t a0, uint32_t a1, uint32_t a2, uint32_t a3,
    uint32_t b0, uint32_t b1) {
    asm volatile(
        "mma.sync.aligned.m16n8k16.row.col.f32.f16.f16.f32 "
        "{%0,%1,%2,%3}, {%4,%5,%6,%7}, {%8,%9}, {%0,%1,%2,%3};"
        : "+f"(c[0]), "+f"(c[1]), "+f"(c[2]), "+f"(c[3])
        : "r"(a0), "r"(a1), "r"(a2), "r"(a3), "r"(b0), "r"(b1));
}
__device__ __forceinline__ void ldmat4(uint32_t r[4], uint32_t addr) {
    asm volatile("ldmatrix.sync.aligned.m8n8.x4.shared.b16 {%0,%1,%2,%3}, [%4];"
        : "=r"(r[0]), "=r"(r[1]), "=r"(r[2]), "=r"(r[3]) : "r"(addr));
}
__device__ __forceinline__ void ldmat4t(uint32_t r[4], uint32_t addr) {
    asm volatile("ldmatrix.sync.aligned.m8n8.x4.trans.shared.b16 {%0,%1,%2,%3}, [%4];"
        : "=r"(r[0]), "=r"(r[1]), "=r"(r[2]), "=r"(r[3]) : "r"(addr));
}
__device__ __forceinline__ uint32_t smem_u32(const void* p) {
    uint32_t a;
    asm("{ .reg .u64 t; cvta.to.shared.u64 t, %1; cvt.u32.u64 %0, t; }"
        : "=r"(a) : "l"(p));
    return a;
}
__device__ __forceinline__ void cp_async16(uint32_t saddr, const void* g) {
    asm volatile("cp.async.ca.shared.global [%0], [%1], 16;"
                 :: "r"(saddr), "l"(g));
}
__device__ __forceinline__ float ex2f(float x) {
    float y;
    asm("ex2.approx.f32 %0, %1;" : "=f"(y) : "f"(x));
    return y;
}
__device__ __forceinline__ uint32_t packh2(float a, float b) {
    __half2 h = __floats2half2_rn(a, b);
    return *(uint32_t*)&h;
}

// ---------------------------------------------------------------------------
// convertAll: pure elementwise fp32 -> fp16 (unchanged, passing)
// ---------------------------------------------------------------------------
__global__ void __launch_bounds__(256) convertAll_kernel(
    const float* __restrict__ q, __half* __restrict__ Xq,
    const float* __restrict__ k, __half* __restrict__ Xk,
    const float* __restrict__ v, __half* __restrict__ Xv,
    const float* __restrict__ Wq, __half* __restrict__ Wqp,
    const float* __restrict__ Wk, __half* __restrict__ Wkp,
    const float* __restrict__ Wv, __half* __restrict__ Wvp)
{
    const int z = blockIdx.z;
    const float* src;
    __half* dst;
    if (z < 24) {
        const int sel = z >> 3, b = z & 7;
        src = (sel == 0 ? q : (sel == 1 ? k : v)) + (size_t)b * 1048576;
        dst = (sel == 0 ? Xq : (sel == 1 ? Xk : Xv)) + (size_t)b * 1048576;
    } else {
        const int sel = z - 24;
        src = sel == 0 ? Wq : (sel == 1 ? Wk : Wv);
        dst = sel == 0 ? Wqp : (sel == 1 ? Wkp : Wvp);
    }
    const float4* s4 = (const float4*)src;
    uint2* d4 = (uint2*)dst;
#pragma unroll
    for (int r = 0; r < 4; r++) {
        int i = blockIdx.x * 1024 + r * 256 + threadIdx.x;
        float4 vv = s4[i];
        uint2 o;
        o.x = packh2(vv.x, vv.y);
        o.y = packh2(vv.z, vv.w);
        d4[i] = o;
    }
}

// ---------------------------------------------------------------------------
// Projection GEMM (unchanged, passing)
// ---------------------------------------------------------------------------
#define PJ_ASTG (128*P64*2)             // 18432
#define PJ_BSTG (64*P128*2)             // 17408
#define PJ_SMEM (3*(PJ_ASTG+PJ_BSTG))   // 107520

__global__ void __launch_bounds__(256, 2) gemm_proj_kernel(
    const __half* __restrict__ Aq, const __half* __restrict__ Bq,
    const float* __restrict__ cq,
    const __half* __restrict__ Ak, const __half* __restrict__ Bk,
    const float* __restrict__ ck,
    const __half* __restrict__ Av, const __half* __restrict__ Bv,
    const float* __restrict__ cv)
{
    extern __shared__ __half smraw[];

    const int gsel = blockIdx.z >> 3;
    const int b = blockIdx.z & 7;
    const __half* Ap    = gsel == 0 ? Aq : (gsel == 1 ? Ak : Av);
    const __half* Bpall = gsel == 0 ? Bq : (gsel == 1 ? Bk : Bv);
    const float* bias   = gsel == 0 ? cq : (gsel == 1 ? ck : cv);

    const int tid = threadIdx.x, wid = tid >> 5, lane = tid & 31;
    const int warp_m = wid & 3, warp_n = wid >> 2;
    const int mBase = blockIdx.y * 128;
    const int nBase = blockIdx.x * 128;

    const __half* Arow = Ap + (size_t)mBase * KPJ;
    const __half* Bp   = Bpall + (size_t)b * CDIM * LDIM;

    const uint32_t sAb = smem_u32(smraw);
    const uint32_t sBb = sAb + 3 * PJ_ASTG;

    const int lrow = lane & 7, lmat = lane >> 3;
    const int a_m = (lmat & 1) * 8 + lrow, a_k = (lmat >> 1) * 8;
    const int bt_r = (lmat & 1) * 8 + lrow;
    const int bt_c = (lmat >> 1) * 8;

    float acc[2][8][4];
#pragma unroll
    for (int mt = 0; mt < 2; mt++)
#pragma unroll
        for (int nt = 0; nt < 8; nt++)
#pragma unroll
            for (int e = 0; e < 4; e++) acc[mt][nt][e] = 0.f;

    const int NIT = KPJ / 64;   // 16

#pragma unroll
    for (int s = 0; s < 2; s++) {
        const int k0 = s * 64;
#pragma unroll
        for (int r = 0; r < 4; r++) {
            int idx = tid + r * 256;
            int row = idx >> 3, u = idx & 7;
            cp_async16(sAb + s*PJ_ASTG + row*(P64*2) + u*16,
                       Arow + (size_t)row*KPJ + k0 + u*8);
        }
#pragma unroll
        for (int r = 0; r < 4; r++) {
            int idx = tid + r * 256;
            int row = idx >> 4, u = idx & 15;
            cp_async16(sBb + s*PJ_BSTG + row*(P128*2) + u*16,
                       Bp + (size_t)(k0 + row)*LDIM + nBase + u*8);
        }
        asm volatile("cp.async.commit_group;");
    }

    for (int it = 0; it < NIT; it++) {
        if (it + 1 < NIT) asm volatile("cp.async.wait_group 1;");
        else              asm volatile("cp.async.wait_group 0;");
        __syncthreads();

        if (it + 2 < NIT) {
            const int stg = (it + 2) % 3, k0 = (it + 2) * 64;
#pragma unroll
            for (int r = 0; r < 4; r++) {
                int idx = tid + r * 256;
                int row = idx >> 3, u = idx & 7;
                cp_async16(sAb + stg*PJ_ASTG + row*(P64*2) + u*16,
                           Arow + (size_t)row*KPJ + k0 + u*8);
            }
#pragma unroll
            for (int r = 0; r < 4; r++) {
                int idx = tid + r * 256;
                int row = idx >> 4, u = idx & 15;
                cp_async16(sBb + stg*PJ_BSTG + row*(P128*2) + u*16,
                           Bp + (size_t)(k0 + row)*LDIM + nBase + u*8);
            }
            asm volatile("cp.async.commit_group;");
        }

        const int st = it % 3;
        const uint32_t uA = sAb + st * PJ_ASTG;
        const uint32_t uB = sBb + st * PJ_BSTG;
#pragma unroll
        for (int ks = 0; ks < 4; ks++) {
            const int kb = ks * 16;
            uint32_t afr[2][4];
#pragma unroll
            for (int mt = 0; mt < 2; mt++)
                ldmat4(afr[mt],
                    uA + ((warp_m*32 + mt*16 + a_m) * P64 + kb + a_k) * 2);
#pragma unroll
            for (int ntp = 0; ntp < 4; ntp++) {
                uint32_t bfr[4];
                ldmat4t(bfr,
                    uB + ((kb + bt_r) * P128 + warp_n*64 + ntp*16 + bt_c) * 2);
                mma16816h(acc[0][2*ntp],   afr[0][0], afr[0][1], afr[0][2], afr[0][3], bfr[0], bfr[1]);
                mma16816h(acc[1][2*ntp],   afr[1][0], afr[1][1], afr[1][2], afr[1][3], bfr[0], bfr[1]);
                mma16816h(acc[0][2*ntp+1], afr[0][0], afr[0][1], afr[0][2], afr[0][3], bfr[2], bfr[3]);
                mma16816h(acc[1][2*ntp+1], afr[1][0], afr[1][1], afr[1][2], afr[1][3], bfr[2], bfr[3]);
            }
        }
    }

    const int qrow = lane >> 2;
    const int qcol = (lane & 3) * 2;

    if (gsel == 2) {
#pragma unroll
        for (int mt = 0; mt < 2; mt++) {
#pragma unroll
            for (int half = 0; half < 2; half++) {
                int o = mBase + warp_m*32 + mt*16 + qrow + half*8;
                int head = o >> 6, c = o & 63;
                float bo = bias[o];
#pragma unroll
                for (int nt = 0; nt < 8; nt++) {
                    int l = nBase + warp_n*64 + nt*8 + qcol;
                    int js = l >> 6, sl = l & 63;
                    __half* row = g_vA +
                        ((size_t)((b*16 + head)*16 + js)*64 + c) * KH;
                    *(uint32_t*)&row[sl] =
                        packh2(acc[mt][nt][half*2+0] + bo,
                               acc[mt][nt][half*2+1] + bo);
                }
            }
        }
    } else {
        __half* g = (gsel == 0) ? g_qT : g_kT;
        const float scl = (gsel == 0) ? (SCALE * L2E) : 1.f;
#pragma unroll
        for (int mt = 0; mt < 2; mt++) {
#pragma unroll
            for (int half = 0; half < 2; half++) {
                int o = mBase + warp_m*32 + mt*16 + qrow + half*8;
                float bo = bias[o];
                __half* row = g + ((size_t)(b*1024 + o)) * LDIM;
#pragma unroll
                for (int nt = 0; nt < 8; nt++) {
                    int l = nBase + warp_n*64 + nt*8 + qcol;
                    *(uint32_t*)&row[l] =
                        packh2((acc[mt][nt][half*2+0] + bo) * scl,
                               (acc[mt][nt][half*2+1] + bo) * scl);
                }
            }
        }
    }
}

// ---------------------------------------------------------------------------
// stats_mma (unchanged, passing)
// ---------------------------------------------------------------------------
#define ST_SK   0
#define ST_SQ   (64*P128*2)
#define ST_RED  (ST_SQ + 2*64*P64*2)
#define ST_SMEM (ST_RED + 2*128*4)

__global__ void __launch_bounds__(256, 2) stats_mma_kernel() {
    extern __shared__ char smx[];
    float* red_z = (float*)(smx + ST_RED);

    const int bh = blockIdx.y;
    const int s0 = blockIdx.x * 128;
    const int tid = threadIdx.x, wid = tid >> 5, lane = tid & 31;
    const int wm = wid & 1, wn = wid >> 1;
    const int qrow = lane >> 2, qc2 = (lane & 3) * 2;
    const int lrow = lane & 7, lmat = lane >> 3;
    const int at_r = (lmat >> 1) * 8 + lrow;
    const int at_c = (lmat & 1) * 8;
    const int bt_r = (lmat & 1) * 8 + lrow;
    const int bt_c = (lmat >> 1) * 8;

    const __half* Kg = g_kT + (size_t)bh * DK * LDIM;
    const __half* Qg = g_qT + (size_t)bh * DK * LDIM;

    const uint32_t sKa = smem_u32(smx + ST_SK);
    const uint32_t sQa = smem_u32(smx + ST_SQ);
    const uint32_t qstage = 64 * P64 * 2;

#pragma unroll
    for (int r = 0; r < 4; r++) {
        int idx = tid + r * 256;
        int row = idx >> 4, u = idx & 15;
        cp_async16(sKa + row * (P128*2) + u * 16,
                   Kg + (size_t)row * LDIM + s0 + u * 8);
    }
#pragma unroll
    for (int r = 0; r < 2; r++) {
        int idx = tid + r * 256;
        int row = idx >> 3, u = idx & 7;
        cp_async16(sQa + row * (P64*2) + u * 16,
                   Qg + (size_t)row * LDIM + u * 8);
    }
    asm volatile("cp.async.commit_group;");

    float Z[8];
#pragma unroll
    for (int i = 0; i < 8; i++) Z[i] = 0.f;

    for (int jt = 0; jt < 16; jt++) {
        const int buf = jt & 1;
        asm volatile("cp.async.wait_group 0;");
        __syncthreads();

        if (jt + 1 < 16) {
            const int nb = (jt + 1) & 1;
            const int tq = (jt + 1) * 64;
#pragma unroll
            for (int r = 0; r < 2; r++) {
                int idx = tid + r * 256;
                int row = idx >> 3, u = idx & 7;
                cp_async16(sQa + nb * qstage + row * (P64*2) + u * 16,
                           Qg + (size_t)row * LDIM + tq + u * 8);
            }
            asm volatile("cp.async.commit_group;");
        }

        const uint32_t uQ = sQa + buf * qstage;
        float sfr[2][4][4];
#pragma unroll
        for (int mt = 0; mt < 2; mt++)
#pragma unroll
            for (int nt = 0; nt < 4; nt++)
#pragma unroll
                for (int e = 0; e < 4; e++) sfr[mt][nt][e] = 0.f;

#pragma unroll
        for (int ks = 0; ks < 4; ks++) {
            const int kb = ks * 16;
            uint32_t afr[2][4];
#pragma unroll
            for (int mt = 0; mt < 2; mt++)
                ldmat4t(afr[mt],
                    uQ + ((kb + at_r) * P64 + wm*32 + mt*16 + at_c) * 2);
#pragma unroll
            for (int ntp = 0; ntp < 2; ntp++) {
                uint32_t bfr[4];
                ldmat4t(bfr,
                    sKa + ((kb + bt_r) * P128 + wn*32 + ntp*16 + bt_c) * 2);
                mma16816h(sfr[0][2*ntp],   afr[0][0], afr[0][1], afr[0][2], afr[0][3], bfr[0], bfr[1]);
                mma16816h(sfr[1][2*ntp],   afr[1][0], afr[1][1], afr[1][2], afr[1][3], bfr[0], bfr[1]);
                mma16816h(sfr[0][2*ntp+1], afr[0][0], afr[0][1], afr[0][2], afr[0][3], bfr[2], bfr[3]);
                mma16816h(sfr[1][2*ntp+1], afr[1][0], afr[1][1], afr[1][2], afr[1][3], bfr[2], bfr[3]);
            }
        }

#pragma unroll
        for (int nt = 0; nt < 4; nt++)
#pragma unroll
            for (int e = 0; e < 2; e++) {
                int i = nt * 2 + e;
                Z[i] += ex2f(sfr[0][nt][e]) + ex2f(sfr[0][nt][e + 2])
                      + ex2f(sfr[1][nt][e]) + ex2f(sfr[1][nt][e + 2]);
            }
    }

#pragma unroll
    for (int ofs = 4; ofs < 32; ofs <<= 1)
#pragma unroll
        for (int i = 0; i < 8; i++)
            Z[i] += __shfl_xor_sync(0xffffffffu, Z[i], ofs);

    if (qrow == 0) {
#pragma unroll
        for (int i = 0; i < 8; i++) {
            int col = wn * 32 + (i >> 1) * 8 + qc2 + (i & 1);
            red_z[wm * 128 + col] = Z[i];
        }
    }
    __syncthreads();
    if (tid < 128) {
        float z = red_z[tid] + red_z[128 + tid];
        g_rz[(size_t)bh * LDIM + s0 + tid] = 1.f / z;
    }
}

// ---------------------------------------------------------------------------
// attnout_mma: software-pipelined — PV(js-1) overlaps exp(js).
// K 2-stage, V 3-stage, P 2-stage. One sync per chunk.
// ---------------------------------------------------------------------------
#define AO_SQ   0                              // [64 c][P128]      17408
#define AO_SK   (AO_SQ + 64*P128*2)            // 2 x [64][P64]     18432
#define AO_SV   (AO_SK + 2*64*P64*2)           // 3 x [64][P64]     27648
#define AO_SP   (AO_SV + 3*64*P64*2)           // 2 x [128][P64]    36864
#define AO_SZ   (AO_SP + 2*128*P64*2)          // 4096
#define AO_SMEM (AO_SZ + 4096)                 // 104448
#define OPITCH 66
#define AO_SO   AO_SK   // fp32 out tile overlays sK/sV (33792 <= 46080)

__global__ void __launch_bounds__(256, 2) attnout_mma_kernel(float* __restrict__ out) {
    extern __shared__ char smx[];
    __half* sP = (__half*)(smx + AO_SP);
    float* sZ = (float*)(smx + AO_SZ);

    const int bh = blockIdx.y;
    const int t0 = blockIdx.x * 128;
    const int tid = threadIdx.x, wid = tid >> 5, lane = tid & 31;
    const int wm = wid & 3, wn = wid >> 2;
    const int qrow = lane >> 2, qc2 = (lane & 3) * 2;
    const int lrow = lane & 7, lmat = lane >> 3;
    const int at_r = (lmat >> 1) * 8 + lrow;
    const int at_c = (lmat & 1) * 8;
    const int bt_r = (lmat & 1) * 8 + lrow;
    const int bt_c = (lmat >> 1) * 8;
    const int a_m = (lmat & 1) * 8 + lrow, a_k = (lmat >> 1) * 8;
    const int b_n = (lmat >> 1) * 8 + lrow, b_k = (lmat & 1) * 8;

    const __half* Qg = g_qT + (size_t)bh * DK * LDIM;
    const __half* Kg = g_kT + (size_t)bh * DK * LDIM;
    const __half* Vg = g_vA + (size_t)bh * 16 * DK * KH;

    const uint32_t sQa = smem_u32(smx + AO_SQ);
    const uint32_t sKa = smem_u32(smx + AO_SK);
    const uint32_t sVa = smem_u32(smx + AO_SV);
    const uint32_t sPa = smem_u32(sP);
    const uint32_t sZa = smem_u32(sZ);
    const uint32_t kstage = 64 * P64 * 2;
    const uint32_t pstage = 128 * P64 * 2;

#pragma unroll
    for (int r = 0; r < 4; r++) {               // Q: 64 rows (c) x 16 u4 (t)
        int idx = tid + r * 256;
        int row = idx >> 4, u = idx & 15;
        cp_async16(sQa + row * (P128*2) + u * 16,
                   Qg + (size_t)row * LDIM + t0 + u * 8);
    }
    {
        const float* zg = g_rz + (size_t)bh * LDIM;
        cp_async16(sZa + tid * 16, zg + tid * 4);
    }
#pragma unroll
    for (int r = 0; r < 2; r++) {               // K0/V0
        int idx = tid + r * 256;
        int row = idx >> 3, u = idx & 7;
        cp_async16(sKa + row * (P64*2) + u * 16,
                   Kg + (size_t)row * LDIM + u * 8);
        cp_async16(sVa + row * (P64*2) + u * 16,
                   Vg + (size_t)row * KH + u * 8);
    }
    asm volatile("cp.async.commit_group;");

    float ofr[2][4][4];
#pragma unroll
    for (int mt = 0; mt < 2; mt++)
#pragma unroll
        for (int nt = 0; nt < 4; nt++)
#pragma unroll
            for (int e = 0; e < 4; e++) ofr[mt][nt][e] = 0.f;

    for (int js = 0; js < 16; js++) {
        asm volatile("cp.async.wait_group 0;");
        __syncthreads();

        if (js + 1 < 16) {
            const int kb2 = ((js + 1) & 1);
            const int vb3 = ((js + 1) % 3);
            const int sq = (js + 1) * 64;
            const __half* Vn = Vg + (size_t)(js + 1) * 64 * KH;
#pragma unroll
            for (int r = 0; r < 2; r++) {
                int idx = tid + r * 256;
                int row = idx >> 3, u = idx & 7;
                cp_async16(sKa + kb2 * kstage + row * (P64*2) + u * 16,
                           Kg + (size_t)row * LDIM + sq + u * 8);
                cp_async16(sVa + vb3 * kstage + row * (P64*2) + u * 16,
                           Vn + (size_t)row * KH + u * 8);
            }
            asm volatile("cp.async.commit_group;");
        }

        // ---- PV for previous chunk (overlaps with S-mma + exp below)
        if (js > 0) {
            const uint32_t uV = sVa + ((js - 1) % 3) * kstage;
            const uint32_t uP = sPa + ((js - 1) & 1) * pstage;
#pragma unroll
            for (int ks = 0; ks < 4; ks++) {
                const int kb = ks * 16;
                uint32_t afr[2][4];
#pragma unroll
                for (int mt = 0; mt < 2; mt++)
                    ldmat4(afr[mt],
                        uP + ((wm*32 + mt*16 + a_m) * P64 + kb + a_k) * 2);
#pragma unroll
                for (int ntp = 0; ntp < 2; ntp++) {
                    uint32_t bfr[4];
                    ldmat4(bfr,
                        uV + ((wn*32 + ntp*16 + b_n) * P64 + kb + b_k) * 2);
                    mma16816h(ofr[0][2*ntp],   afr[0][0], afr[0][1], afr[0][2], afr[0][3], bfr[0], bfr[1]);
                    mma16816h(ofr[1][2*ntp],   afr[1][0], afr[1][1], afr[1][2], afr[1][3], bfr[0], bfr[1]);
                    mma16816h(ofr[0][2*ntp+1], afr[0][0], afr[0][1], afr[0][2], afr[0][3], bfr[2], bfr[3]);
                    mma16816h(ofr[1][2*ntp+1], afr[1][0], afr[1][1], afr[1][2], afr[1][3], bfr[2], bfr[3]);
                }
            }
        }

        // ---- S' = q . k  (current chunk)
        const uint32_t uK = sKa + (js & 1) * kstage;
        float sfr[2][4][4];
#pragma unroll
        for (int mt = 0; mt < 2; mt++)
#pragma unroll
            for (int nt = 0; nt < 4; nt++)
#pragma unroll
                for (int e = 0; e < 4; e++) sfr[mt][nt][e] = 0.f;

#pragma unroll
        for (int ks = 0; ks < 4; ks++) {
            const int kb = ks * 16;
            uint32_t afr[2][4];
#pragma unroll
            for (int mt = 0; mt < 2; mt++)
                ldmat4t(afr[mt],
                    sQa + ((kb + at_r) * P128 + wm*32 + mt*16 + at_c) * 2);
#pragma unroll
            for (int ntp = 0; ntp < 2; ntp++) {
                uint32_t bfr[4];
                ldmat4t(bfr,
                    uK + ((kb + bt_r) * P64 + wn*32 + ntp*16 + bt_c) * 2);
                mma16816h(sfr[0][2*ntp],   afr[0][0], afr[0][1], afr[0][2], afr[0][3], bfr[0], bfr[1]);
                mma16816h(sfr[1][2*ntp],   afr[1][0], afr[1][1], afr[1][2], afr[1][3], bfr[0], bfr[1]);
                mma16816h(sfr[0][2*ntp+1], afr[0][0], afr[0][1], afr[0][2], afr[0][3], bfr[2], bfr[3]);
                mma16816h(sfr[1][2*ntp+1], afr[1][0], afr[1][1], afr[1][2], afr[1][3], bfr[2], bfr[3]);
            }
        }

        // ---- P = ex2(S') * rz -> fp16 sP[js&1]
        __half* sPw = sP + (js & 1) * 128 * P64;
#pragma unroll
        for (int nt = 0; nt < 4; nt++) {
            int cp0 = wn * 32 + nt * 8 + qc2;
            float z0v = sZ[js * 64 + cp0], z1v = sZ[js * 64 + cp0 + 1];
#pragma unroll
            for (int mt = 0; mt < 2; mt++) {
                int trow = wm * 32 + mt * 16 + qrow;
#pragma unroll
                for (int rr = 0; rr < 2; rr++) {
                    int t = trow + rr * 8;
                    float p0 = ex2f(sfr[mt][nt][rr * 2 + 0]) * z0v;
                    float p1 = ex2f(sfr[mt][nt][rr * 2 + 1]) * z1v;
                    *(uint32_t*)&sPw[t * P64 + cp0] = packh2(p0, p1);
                }
            }
        }
    }

    // ---- final PV (chunk 15)
    __syncthreads();
    {
        const uint32_t uV = sVa + (15 % 3) * kstage;
        const uint32_t uP = sPa + (15 & 1) * pstage;
#pragma unroll
        for (int ks = 0; ks < 4; ks++) {
            const int kb = ks * 16;
            uint32_t afr[2][4];
#pragma unroll
            for (int mt = 0; mt < 2; mt++)
                ldmat4(afr[mt],
                    uP + ((wm*32 + mt*16 + a_m) * P64 + kb + a_k) * 2);
#pragma unroll
            for (int ntp = 0; ntp < 2; ntp++) {
                uint32_t bfr[4];
                ldmat4(bfr,
                    uV + ((wn*32 + ntp*16 + b_n) * P64 + kb + b_k) * 2);
                mma16816h(ofr[0][2*ntp],   afr[0][0], afr[0][1], afr[0][2], afr[0][3], bfr[0], bfr[1]);
                mma16816h(ofr[1][2*ntp],   afr[1][0], afr[1][1], afr[1][2], afr[1][3], bfr[0], bfr[1]);
                mma16816h(ofr[0][2*ntp+1], afr[0][0], afr[0][1], afr[0][2], afr[0][3], bfr[2], bfr[3]);
                mma16816h(ofr[1][2*ntp+1], afr[1][0], afr[1][1], afr[1][2], afr[1][3], bfr[2], bfr[3]);
            }
        }
    }

    // epilogue: stage fp32 out tile (overlays sK/sV), transposed store
    __syncthreads();
    float* sO = (float*)(smx + AO_SO);
#pragma unroll
    for (int mt = 0; mt < 2; mt++) {
        int trow = wm * 32 + mt * 16 + qrow;
#pragma unroll
        for (int nt = 0; nt < 4; nt++) {
            int c = wn * 32 + nt * 8 + qc2;
            *(float2*)&sO[trow * OPITCH + c] =
                make_float2(ofr[mt][nt][0], ofr[mt][nt][1]);
            *(float2*)&sO[(trow + 8) * OPITCH + c] =
                make_float2(ofr[mt][nt][2], ofr[mt][nt][3]);
        }
    }
    __syncthreads();
    {
        int c = tid >> 2, seg = tid & 3;
        float* op = out + (size_t)bh * DK * LDIM + (size_t)c * LDIM + t0;
#pragma unroll
        for (int i = 0; i < 8; i++) {
            int t = seg * 32 + i * 4;
            float4 vv;
            vv.x = sO[(t + 0) * OPITCH + c];
            vv.y = sO[(t + 1) * OPITCH + c];
            vv.z = sO[(t + 2) * OPITCH + c];
            vv.w = sO[(t + 3) * OPITCH + c];
            *(float4*)(op + t) = vv;
        }
    }
}

// ---------------------------------------------------------------------------
extern "C" void kernel_launch(void* const* d_in, const int* in_sizes, int n_in,
                              void* d_out, int out_size) {
    (void)in_sizes; (void)n_in; (void)out_size;
    const float* q  = (const float*)d_in[0];
    const float* k  = (const float*)d_in[1];
    const float* v  = (const float*)d_in[2];
    const float* Wq = (const float*)d_in[3];
    const float* bq = (const float*)d_in[4];
    const float* Wk = (const float*)d_in[5];
    const float* bk = (const float*)d_in[6];
    const float* Wv = (const float*)d_in[7];
    const float* bv = (const float*)d_in[8];
    float* out = (float*)d_out;

    __half *p_Wqp, *p_Wkp, *p_Wvp, *p_Xqp, *p_Xkp, *p_Xvp;
    cudaGetSymbolAddress((void**)&p_Wqp, g_Wqp);
    cudaGetSymbolAddress((void**)&p_Wkp, g_Wkp);
    cudaGetSymbolAddress((void**)&p_Wvp, g_Wvp);
    cudaGetSymbolAddress((void**)&p_Xqp, g_Xqp);
    cudaGetSymbolAddress((void**)&p_Xkp, g_Xkp);
    cudaGetSymbolAddress((void**)&p_Xvp, g_Xvp);

    cudaFuncSetAttribute(gemm_proj_kernel,
        cudaFuncAttributeMaxDynamicSharedMemorySize, PJ_SMEM);
    cudaFuncSetAttribute(stats_mma_kernel,
        cudaFuncAttributeMaxDynamicSharedMemorySize, ST_SMEM);
    cudaFuncSetAttribute(attnout_mma_kernel,
        cudaFuncAttributeMaxDynamicSharedMemorySize, AO_SMEM);

    convertAll_kernel<<<dim3(256, 1, 27), 256>>>(
        q, p_Xqp, k, p_Xkp, v, p_Xvp,
        Wq, p_Wqp, Wk, p_Wkp, Wv, p_Wvp);                               // 0

    gemm_proj_kernel<<<dim3(LDIM/128, CDIM/128, 24), 256, PJ_SMEM>>>(
        p_Wqp, p_Xqp, bq,
        p_Wkp, p_Xkp, bk,
        p_Wvp, p_Xvp, bv);                                              // 1

    stats_mma_kernel<<<dim3(LDIM/128, NH), 256, ST_SMEM>>>();           // 2
    attnout_mma_kernel<<<dim3(LDIM/128, NH), 256, AO_SMEM>>>(out);      // 3 (profiled)
}

// round 16
// speedup vs baseline: 1.0331x; 1.0331x over previous
#include <cuda_runtime.h>
#include <cuda_bf16.h>
#include <cuda_fp16.h>
#include <cstdint>

#define BDIM 8
#define CDIM 1024
#define LDIM 1024
#define HDIM 16
#define DK   64
#define NH   (BDIM*HDIM)
#define SCALE 0.125f
#define L2E   1.44269504f
#define KPJ  1024
#define KH   64
#define P64  72              // pitch for 64-wide fp16 rows
#define P128 136             // pitch for 128-wide fp16 rows

// ---------------- scratch (device globals; no allocation allowed) ----------
static __device__ float g_rz[NH*LDIM];

static __device__ __half g_Wqp[CDIM*KPJ];
static __device__ __half g_Wkp[CDIM*KPJ];
static __device__ __half g_Wvp[CDIM*KPJ];
static __device__ __half g_Xqp[BDIM*CDIM*LDIM];  // [b][c][l] fp16
static __device__ __half g_Xkp[BDIM*CDIM*LDIM];
static __device__ __half g_Xvp[BDIM*CDIM*LDIM];

static __device__ __half g_qT[NH*DK*LDIM];       // [bh][c][t] * SCALE*log2e
static __device__ __half g_kT[NH*DK*LDIM];       // [bh][c][s]
static __device__ __half g_vA[NH*16*DK*KH];      // [bh][s>>6][c][sl]

// ---------------------------------------------------------------------------
// helpers
// ---------------------------------------------------------------------------
__device__ __forceinline__ void mma16816h(float c[4],
    uint32_t a0, uint32_t a1, uint32_t a2, uint32_t a3,
    uint32_t b0, uint32_t b1) {
    asm volatile(
        "mma.sync.aligned.m16n8k16.row.col.f32.f16.f16.f32 "
        "{%0,%1,%2,%3}, {%4,%5,%6,%7}, {%8,%9}, {%0,%1,%2,%3};"
        : "+f"(c[0]), "+f"(c[1]), "+f"(c[2]), "+f"(c[3])
        : "r"(a0), "r"(a1), "r"(a2), "r"(a3), "r"(b0), "r"(b1));
}
__device__ __forceinline__ void ldmat4(uint32_t r[4], uint32_t addr) {
    asm volatile("ldmatrix.sync.aligned.m8n8.x4.shared.b16 {%0,%1,%2,%3}, [%4];"
        : "=r"(r[0]), "=r"(r[1]), "=r"(r[2]), "=r"(r[3]) : "r"(addr));
}
__device__ __forceinline__ void ldmat4t(uint32_t r[4], uint32_t addr) {
    asm volatile("ldmatrix.sync.aligned.m8n8.x4.trans.shared.b16 {%0,%1,%2,%3}, [%4];"
        : "=r"(r[0]), "=r"(r[1]), "=r"(r[2]), "=r"(r[3]) : "r"(addr));
}
__device__ __forceinline__ uint32_t smem_u32(const void* p) {
    uint32_t a;
    asm("{ .reg .u64 t; cvta.to.shared.u64 t, %1; cvt.u32.u64 %0, t; }"
        : "=r"(a) : "l"(p));
    return a;
}
__device__ __forceinline__ void cp_async16(uint32_t saddr, const void* g) {
    asm volatile("cp.async.ca.shared.global [%0], [%1], 16;"
                 :: "r"(saddr), "l"(g));
}
__device__ __forceinline__ float ex2f(float x) {
    float y;
    asm("ex2.approx.f32 %0, %1;" : "=f"(y) : "f"(x));
    return y;
}
__device__ __forceinline__ uint32_t packh2(float a, float b) {
    __half2 h = __floats2half2_rn(a, b);
    return *(uint32_t*)&h;
}

// ---------------------------------------------------------------------------
// convertAll: pure elementwise fp32 -> fp16 (unchanged, passing)
// ---------------------------------------------------------------------------
__global__ void __launch_bounds__(256) convertAll_kernel(
    const float* __restrict__ q, __half* __restrict__ Xq,
    const float* __restrict__ k, __half* __restrict__ Xk,
    const float* __restrict__ v, __half* __restrict__ Xv,
    const float* __restrict__ Wq, __half* __restrict__ Wqp,
    const float* __restrict__ Wk, __half* __restrict__ Wkp,
    const float* __restrict__ Wv, __half* __restrict__ Wvp)
{
    const int z = blockIdx.z;
    const float* src;
    __half* dst;
    if (z < 24) {
        const int sel = z >> 3, b = z & 7;
        src = (sel == 0 ? q : (sel == 1 ? k : v)) + (size_t)b * 1048576;
        dst = (sel == 0 ? Xq : (sel == 1 ? Xk : Xv)) + (size_t)b * 1048576;
    } else {
        const int sel = z - 24;
        src = sel == 0 ? Wq : (sel == 1 ? Wk : Wv);
        dst = sel == 0 ? Wqp : (sel == 1 ? Wkp : Wvp);
    }
    const float4* s4 = (const float4*)src;
    uint2* d4 = (uint2*)dst;
#pragma unroll
    for (int r = 0; r < 4; r++) {
        int i = blockIdx.x * 1024 + r * 256 + threadIdx.x;
        float4 vv = s4[i];
        uint2 o;
        o.x = packh2(vv.x, vv.y);
        o.y = packh2(vv.z, vv.w);
        d4[i] = o;
    }
}

// ---------------------------------------------------------------------------
// Projection GEMM (unchanged, passing)
// ---------------------------------------------------------------------------
#define PJ_ASTG (128*P64*2)
#define PJ_BSTG (64*P128*2)
#define PJ_SMEM (3*(PJ_ASTG+PJ_BSTG))

__global__ void __launch_bounds__(256, 2) gemm_proj_kernel(
    const __half* __restrict__ Aq, const __half* __restrict__ Bq,
    const float* __restrict__ cq,
    const __half* __restrict__ Ak, const __half* __restrict__ Bk,
    const float* __restrict__ ck,
    const __half* __restrict__ Av, const __half* __restrict__ Bv,
    const float* __restrict__ cv)
{
    extern __shared__ __half smraw[];

    const int gsel = blockIdx.z >> 3;
    const int b = blockIdx.z & 7;
    const __half* Ap    = gsel == 0 ? Aq : (gsel == 1 ? Ak : Av);
    const __half* Bpall = gsel == 0 ? Bq : (gsel == 1 ? Bk : Bv);
    const float* bias   = gsel == 0 ? cq : (gsel == 1 ? ck : cv);

    const int tid = threadIdx.x, wid = tid >> 5, lane = tid & 31;
    const int warp_m = wid & 3, warp_n = wid >> 2;
    const int mBase = blockIdx.y * 128;
    const int nBase = blockIdx.x * 128;

    const __half* Arow = Ap + (size_t)mBase * KPJ;
    const __half* Bp   = Bpall + (size_t)b * CDIM * LDIM;

    const uint32_t sAb = smem_u32(smraw);
    const uint32_t sBb = sAb + 3 * PJ_ASTG;

    const int lrow = lane & 7, lmat = lane >> 3;
    const int a_m = (lmat & 1) * 8 + lrow, a_k = (lmat >> 1) * 8;
    const int bt_r = (lmat & 1) * 8 + lrow;
    const int bt_c = (lmat >> 1) * 8;

    float acc[2][8][4];
#pragma unroll
    for (int mt = 0; mt < 2; mt++)
#pragma unroll
        for (int nt = 0; nt < 8; nt++)
#pragma unroll
            for (int e = 0; e < 4; e++) acc[mt][nt][e] = 0.f;

    const int NIT = KPJ / 64;   // 16

#pragma unroll
    for (int s = 0; s < 2; s++) {
        const int k0 = s * 64;
#pragma unroll
        for (int r = 0; r < 4; r++) {
            int idx = tid + r * 256;
            int row = idx >> 3, u = idx & 7;
            cp_async16(sAb + s*PJ_ASTG + row*(P64*2) + u*16,
                       Arow + (size_t)row*KPJ + k0 + u*8);
        }
#pragma unroll
        for (int r = 0; r < 4; r++) {
            int idx = tid + r * 256;
            int row = idx >> 4, u = idx & 15;
            cp_async16(sBb + s*PJ_BSTG + row*(P128*2) + u*16,
                       Bp + (size_t)(k0 + row)*LDIM + nBase + u*8);
        }
        asm volatile("cp.async.commit_group;");
    }

    for (int it = 0; it < NIT; it++) {
        if (it + 1 < NIT) asm volatile("cp.async.wait_group 1;");
        else              asm volatile("cp.async.wait_group 0;");
        __syncthreads();

        if (it + 2 < NIT) {
            const int stg = (it + 2) % 3, k0 = (it + 2) * 64;
#pragma unroll
            for (int r = 0; r < 4; r++) {
                int idx = tid + r * 256;
                int row = idx >> 3, u = idx & 7;
                cp_async16(sAb + stg*PJ_ASTG + row*(P64*2) + u*16,
                           Arow + (size_t)row*KPJ + k0 + u*8);
            }
#pragma unroll
            for (int r = 0; r < 4; r++) {
                int idx = tid + r * 256;
                int row = idx >> 4, u = idx & 15;
                cp_async16(sBb + stg*PJ_BSTG + row*(P128*2) + u*16,
                           Bp + (size_t)(k0 + row)*LDIM + nBase + u*8);
            }
            asm volatile("cp.async.commit_group;");
        }

        const int st = it % 3;
        const uint32_t uA = sAb + st * PJ_ASTG;
        const uint32_t uB = sBb + st * PJ_BSTG;
#pragma unroll
        for (int ks = 0; ks < 4; ks++) {
            const int kb = ks * 16;
            uint32_t afr[2][4];
#pragma unroll
            for (int mt = 0; mt < 2; mt++)
                ldmat4(afr[mt],
                    uA + ((warp_m*32 + mt*16 + a_m) * P64 + kb + a_k) * 2);
#pragma unroll
            for (int ntp = 0; ntp < 4; ntp++) {
                uint32_t bfr[4];
                ldmat4t(bfr,
                    uB + ((kb + bt_r) * P128 + warp_n*64 + ntp*16 + bt_c) * 2);
                mma16816h(acc[0][2*ntp],   afr[0][0], afr[0][1], afr[0][2], afr[0][3], bfr[0], bfr[1]);
                mma16816h(acc[1][2*ntp],   afr[1][0], afr[1][1], afr[1][2], afr[1][3], bfr[0], bfr[1]);
                mma16816h(acc[0][2*ntp+1], afr[0][0], afr[0][1], afr[0][2], afr[0][3], bfr[2], bfr[3]);
                mma16816h(acc[1][2*ntp+1], afr[1][0], afr[1][1], afr[1][2], afr[1][3], bfr[2], bfr[3]);
            }
        }
    }

    const int qrow = lane >> 2;
    const int qcol = (lane & 3) * 2;

    if (gsel == 2) {
#pragma unroll
        for (int mt = 0; mt < 2; mt++) {
#pragma unroll
            for (int half = 0; half < 2; half++) {
                int o = mBase + warp_m*32 + mt*16 + qrow + half*8;
                int head = o >> 6, c = o & 63;
                float bo = bias[o];
#pragma unroll
                for (int nt = 0; nt < 8; nt++) {
                    int l = nBase + warp_n*64 + nt*8 + qcol;
                    int js = l >> 6, sl = l & 63;
                    __half* row = g_vA +
                        ((size_t)((b*16 + head)*16 + js)*64 + c) * KH;
                    *(uint32_t*)&row[sl] =
                        packh2(acc[mt][nt][half*2+0] + bo,
                               acc[mt][nt][half*2+1] + bo);
                }
            }
        }
    } else {
        __half* g = (gsel == 0) ? g_qT : g_kT;
        const float scl = (gsel == 0) ? (SCALE * L2E) : 1.f;
#pragma unroll
        for (int mt = 0; mt < 2; mt++) {
#pragma unroll
            for (int half = 0; half < 2; half++) {
                int o = mBase + warp_m*32 + mt*16 + qrow + half*8;
                float bo = bias[o];
                __half* row = g + ((size_t)(b*1024 + o)) * LDIM;
#pragma unroll
                for (int nt = 0; nt < 8; nt++) {
                    int l = nBase + warp_n*64 + nt*8 + qcol;
                    *(uint32_t*)&row[l] =
                        packh2((acc[mt][nt][half*2+0] + bo) * scl,
                               (acc[mt][nt][half*2+1] + bo) * scl);
                }
            }
        }
    }
}

// ---------------------------------------------------------------------------
// stats_mma (unchanged, passing)
// ---------------------------------------------------------------------------
#define ST_SK   0
#define ST_SQ   (64*P128*2)
#define ST_RED  (ST_SQ + 2*64*P64*2)
#define ST_SMEM (ST_RED + 2*128*4)

__global__ void __launch_bounds__(256, 2) stats_mma_kernel() {
    extern __shared__ char smx[];
    float* red_z = (float*)(smx + ST_RED);

    const int bh = blockIdx.y;
    const int s0 = blockIdx.x * 128;
    const int tid = threadIdx.x, wid = tid >> 5, lane = tid & 31;
    const int wm = wid & 1, wn = wid >> 1;
    const int qrow = lane >> 2, qc2 = (lane & 3) * 2;
    const int lrow = lane & 7, lmat = lane >> 3;
    const int at_r = (lmat >> 1) * 8 + lrow;
    const int at_c = (lmat & 1) * 8;
    const int bt_r = (lmat & 1) * 8 + lrow;
    const int bt_c = (lmat >> 1) * 8;

    const __half* Kg = g_kT + (size_t)bh * DK * LDIM;
    const __half* Qg = g_qT + (size_t)bh * DK * LDIM;

    const uint32_t sKa = smem_u32(smx + ST_SK);
    const uint32_t sQa = smem_u32(smx + ST_SQ);
    const uint32_t qstage = 64 * P64 * 2;

#pragma unroll
    for (int r = 0; r < 4; r++) {
        int idx = tid + r * 256;
        int row = idx >> 4, u = idx & 15;
        cp_async16(sKa + row * (P128*2) + u * 16,
                   Kg + (size_t)row * LDIM + s0 + u * 8);
    }
#pragma unroll
    for (int r = 0; r < 2; r++) {
        int idx = tid + r * 256;
        int row = idx >> 3, u = idx & 7;
        cp_async16(sQa + row * (P64*2) + u * 16,
                   Qg + (size_t)row * LDIM + u * 8);
    }
    asm volatile("cp.async.commit_group;");

    float Z[8];
#pragma unroll
    for (int i = 0; i < 8; i++) Z[i] = 0.f;

    for (int jt = 0; jt < 16; jt++) {
        const int buf = jt & 1;
        asm volatile("cp.async.wait_group 0;");
        __syncthreads();

        if (jt + 1 < 16) {
            const int nb = (jt + 1) & 1;
            const int tq = (jt + 1) * 64;
#pragma unroll
            for (int r = 0; r < 2; r++) {
                int idx = tid + r * 256;
                int row = idx >> 3, u = idx & 7;
                cp_async16(sQa + nb * qstage + row * (P64*2) + u * 16,
                           Qg + (size_t)row * LDIM + tq + u * 8);
            }
            asm volatile("cp.async.commit_group;");
        }

        const uint32_t uQ = sQa + buf * qstage;
        float sfr[2][4][4];
#pragma unroll
        for (int mt = 0; mt < 2; mt++)
#pragma unroll
            for (int nt = 0; nt < 4; nt++)
#pragma unroll
                for (int e = 0; e < 4; e++) sfr[mt][nt][e] = 0.f;

#pragma unroll
        for (int ks = 0; ks < 4; ks++) {
            const int kb = ks * 16;
            uint32_t afr[2][4];
#pragma unroll
            for (int mt = 0; mt < 2; mt++)
                ldmat4t(afr[mt],
                    uQ + ((kb + at_r) * P64 + wm*32 + mt*16 + at_c) * 2);
#pragma unroll
            for (int ntp = 0; ntp < 2; ntp++) {
                uint32_t bfr[4];
                ldmat4t(bfr,
                    sKa + ((kb + bt_r) * P128 + wn*32 + ntp*16 + bt_c) * 2);
                mma16816h(sfr[0][2*ntp],   afr[0][0], afr[0][1], afr[0][2], afr[0][3], bfr[0], bfr[1]);
                mma16816h(sfr[1][2*ntp],   afr[1][0], afr[1][1], afr[1][2], afr[1][3], bfr[0], bfr[1]);
                mma16816h(sfr[0][2*ntp+1], afr[0][0], afr[0][1], afr[0][2], afr[0][3], bfr[2], bfr[3]);
                mma16816h(sfr[1][2*ntp+1], afr[1][0], afr[1][1], afr[1][2], afr[1][3], bfr[2], bfr[3]);
            }
        }

#pragma unroll
        for (int nt = 0; nt < 4; nt++)
#pragma unroll
            for (int e = 0; e < 2; e++) {
                int i = nt * 2 + e;
                Z[i] += ex2f(sfr[0][nt][e]) + ex2f(sfr[0][nt][e + 2])
                      + ex2f(sfr[1][nt][e]) + ex2f(sfr[1][nt][e + 2]);
            }
    }

#pragma unroll
    for (int ofs = 4; ofs < 32; ofs <<= 1)
#pragma unroll
        for (int i = 0; i < 8; i++)
            Z[i] += __shfl_xor_sync(0xffffffffu, Z[i], ofs);

    if (qrow == 0) {
#pragma unroll
        for (int i = 0; i < 8; i++) {
            int col = wn * 32 + (i >> 1) * 8 + qc2 + (i & 1);
            red_z[wm * 128 + col] = Z[i];
        }
    }
    __syncthreads();
    if (tid < 128) {
        float z = red_z[tid] + red_z[128 + tid];
        g_rz[(size_t)bh * LDIM + s0 + tid] = 1.f / z;
    }
}

// ---------------------------------------------------------------------------
// attnout_mma: P kept in registers. Warp w owns t-tile [w*16, w*16+16),
// computes full N=64 S tile, exp+pack -> PV A-fragments directly.
// One __syncthreads per chunk. No P smem.
// ---------------------------------------------------------------------------
#define AO_SQ   0                              // [64 c][P128]      17408
#define AO_SK   (AO_SQ + 64*P128*2)            // 2 x [64][P64]     18432
#define AO_SV   (AO_SK + 2*64*P64*2)           // 18432
#define AO_SZ   (AO_SV + 2*64*P64*2)           // 4096
#define AO_SMEM (AO_SZ + 4096)                 // 62464
#define OPITCH 66
#define AO_SO   AO_SK   // fp32 out tile overlays sK/sV (33792 <= 36864)

__global__ void __launch_bounds__(256, 2) attnout_mma_kernel(float* __restrict__ out) {
    extern __shared__ char smx[];
    float* sZ = (float*)(smx + AO_SZ);

    const int bh = blockIdx.y;
    const int t0 = blockIdx.x * 128;
    const int tid = threadIdx.x, wid = tid >> 5, lane = tid & 31;
    const int qrow = lane >> 2, qc2 = (lane & 3) * 2;
    const int lrow = lane & 7, lmat = lane >> 3;
    const int at_r = (lmat >> 1) * 8 + lrow;   // trans-A: k row
    const int at_c = (lmat & 1) * 8;           // trans-A: m col
    const int bt_r = (lmat & 1) * 8 + lrow;    // trans-B: k row
    const int bt_c = (lmat >> 1) * 8;          // trans-B: n col
    const int b_n = (lmat >> 1) * 8 + lrow;    // non-trans B: n row
    const int b_k = (lmat & 1) * 8;            // non-trans B: k col

    const __half* Qg = g_qT + (size_t)bh * DK * LDIM;   // [c][t]
    const __half* Kg = g_kT + (size_t)bh * DK * LDIM;   // [c][s]
    const __half* Vg = g_vA + (size_t)bh * 16 * DK * KH;

    const uint32_t sQa = smem_u32(smx + AO_SQ);
    const uint32_t sKa = smem_u32(smx + AO_SK);
    const uint32_t sVa = smem_u32(smx + AO_SV);
    const uint32_t sZa = smem_u32(sZ);
    const uint32_t kstage = 64 * P64 * 2;

#pragma unroll
    for (int r = 0; r < 4; r++) {               // Q: 64 rows (c) x 16 u4 (t)
        int idx = tid + r * 256;
        int row = idx >> 4, u = idx & 15;
        cp_async16(sQa + row * (P128*2) + u * 16,
                   Qg + (size_t)row * LDIM + t0 + u * 8);
    }
    {
        const float* zg = g_rz + (size_t)bh * LDIM;
        cp_async16(sZa + tid * 16, zg + tid * 4);
    }
#pragma unroll
    for (int r = 0; r < 2; r++) {               // K0/V0
        int idx = tid + r * 256;
        int row = idx >> 3, u = idx & 7;
        cp_async16(sKa + row * (P64*2) + u * 16,
                   Kg + (size_t)row * LDIM + u * 8);
        cp_async16(sVa + row * (P64*2) + u * 16,
                   Vg + (size_t)row * KH + u * 8);
    }
    asm volatile("cp.async.commit_group;");

    float ofr[8][4];
#pragma unroll
    for (int nt = 0; nt < 8; nt++)
#pragma unroll
        for (int e = 0; e < 4; e++) ofr[nt][e] = 0.f;

    for (int js = 0; js < 16; js++) {
        asm volatile("cp.async.wait_group 0;");
        __syncthreads();

        if (js + 1 < 16) {
            const int nb = (js + 1) & 1;
            const int sq = (js + 1) * 64;
            const __half* Vn = Vg + (size_t)(js + 1) * 64 * KH;
#pragma unroll
            for (int r = 0; r < 2; r++) {
                int idx = tid + r * 256;
                int row = idx >> 3, u = idx & 7;
                cp_async16(sKa + nb * kstage + row * (P64*2) + u * 16,
                           Kg + (size_t)row * LDIM + sq + u * 8);
                cp_async16(sVa + nb * kstage + row * (P64*2) + u * 16,
                           Vn + (size_t)row * KH + u * 8);
            }
            asm volatile("cp.async.commit_group;");
        }

        const uint32_t uK = sKa + (js & 1) * kstage;
        const uint32_t uV = sVa + (js & 1) * kstage;

        // ---- S' = q . k  (M=16 per warp, N=64, K=64)
        float sfr[8][4];
#pragma unroll
        for (int nt = 0; nt < 8; nt++)
#pragma unroll
            for (int e = 0; e < 4; e++) sfr[nt][e] = 0.f;

#pragma unroll
        for (int ks = 0; ks < 4; ks++) {
            const int kb = ks * 16;
            uint32_t afr[4];
            ldmat4t(afr, sQa + ((kb + at_r) * P128 + wid*16 + at_c) * 2);
#pragma unroll
            for (int ntp = 0; ntp < 4; ntp++) {
                uint32_t bfr[4];
                ldmat4t(bfr, uK + ((kb + bt_r) * P64 + ntp*16 + bt_c) * 2);
                mma16816h(sfr[2*ntp],   afr[0], afr[1], afr[2], afr[3], bfr[0], bfr[1]);
                mma16816h(sfr[2*ntp+1], afr[0], afr[1], afr[2], afr[3], bfr[2], bfr[3]);
            }
        }

        // ---- PV: a-fragments built in registers from exp(S')
#pragma unroll
        for (int kk = 0; kk < 4; kk++) {
            float z0 = sZ[js*64 + kk*16 + qc2];
            float z1 = sZ[js*64 + kk*16 + qc2 + 1];
            float z2 = sZ[js*64 + kk*16 + 8 + qc2];
            float z3 = sZ[js*64 + kk*16 + 8 + qc2 + 1];
            uint32_t a0 = packh2(ex2f(sfr[2*kk][0]) * z0,
                                 ex2f(sfr[2*kk][1]) * z1);
            uint32_t a1 = packh2(ex2f(sfr[2*kk][2]) * z0,
                                 ex2f(sfr[2*kk][3]) * z1);
            uint32_t a2 = packh2(ex2f(sfr[2*kk+1][0]) * z2,
                                 ex2f(sfr[2*kk+1][1]) * z3);
            uint32_t a3 = packh2(ex2f(sfr[2*kk+1][2]) * z2,
                                 ex2f(sfr[2*kk+1][3]) * z3);
#pragma unroll
            for (int ntp = 0; ntp < 4; ntp++) {
                uint32_t bfr[4];
                ldmat4(bfr, uV + ((ntp*16 + b_n) * P64 + kk*16 + b_k) * 2);
                mma16816h(ofr[2*ntp],   a0, a1, a2, a3, bfr[0], bfr[1]);
                mma16816h(ofr[2*ntp+1], a0, a1, a2, a3, bfr[2], bfr[3]);
            }
        }
    }

    // epilogue: stage fp32 out tile (overlays sK/sV), transposed store
    __syncthreads();
    float* sO = (float*)(smx + AO_SO);
    {
        int trow = wid * 16 + qrow;
#pragma unroll
        for (int nt = 0; nt < 8; nt++) {
            int c = nt * 8 + qc2;
            *(float2*)&sO[trow * OPITCH + c] =
                make_float2(ofr[nt][0], ofr[nt][1]);
            *(float2*)&sO[(trow + 8) * OPITCH + c] =
                make_float2(ofr[nt][2], ofr[nt][3]);
        }
    }
    __syncthreads();
    {
        int c = tid >> 2, seg = tid & 3;
        float* op = out + (size_t)bh * DK * LDIM + (size_t)c * LDIM + t0;
#pragma unroll
        for (int i = 0; i < 8; i++) {
            int t = seg * 32 + i * 4;
            float4 vv;
            vv.x = sO[(t + 0) * OPITCH + c];
            vv.y = sO[(t + 1) * OPITCH + c];
            vv.z = sO[(t + 2) * OPITCH + c];
            vv.w = sO[(t + 3) * OPITCH + c];
            *(float4*)(op + t) = vv;
        }
    }
}

// ---------------------------------------------------------------------------
extern "C" void kernel_launch(void* const* d_in, const int* in_sizes, int n_in,
                              void* d_out, int out_size) {
    (void)in_sizes; (void)n_in; (void)out_size;
    const float* q  = (const float*)d_in[0];
    const float* k  = (const float*)d_in[1];
    const float* v  = (const float*)d_in[2];
    const float* Wq = (const float*)d_in[3];
    const float* bq = (const float*)d_in[4];
    const float* Wk = (const float*)d_in[5];
    const float* bk = (const float*)d_in[6];
    const float* Wv = (const float*)d_in[7];
    const float* bv = (const float*)d_in[8];
    float* out = (float*)d_out;

    __half *p_Wqp, *p_Wkp, *p_Wvp, *p_Xqp, *p_Xkp, *p_Xvp;
    cudaGetSymbolAddress((void**)&p_Wqp, g_Wqp);
    cudaGetSymbolAddress((void**)&p_Wkp, g_Wkp);
    cudaGetSymbolAddress((void**)&p_Wvp, g_Wvp);
    cudaGetSymbolAddress((void**)&p_Xqp, g_Xqp);
    cudaGetSymbolAddress((void**)&p_Xkp, g_Xkp);
    cudaGetSymbolAddress((void**)&p_Xvp, g_Xvp);

    cudaFuncSetAttribute(gemm_proj_kernel,
        cudaFuncAttributeMaxDynamicSharedMemorySize, PJ_SMEM);
    cudaFuncSetAttribute(stats_mma_kernel,
        cudaFuncAttributeMaxDynamicSharedMemorySize, ST_SMEM);
    cudaFuncSetAttribute(attnout_mma_kernel,
        cudaFuncAttributeMaxDynamicSharedMemorySize, AO_SMEM);

    convertAll_kernel<<<dim3(256, 1, 27), 256>>>(
        q, p_Xqp, k, p_Xkp, v, p_Xvp,
        Wq, p_Wqp, Wk, p_Wkp, Wv, p_Wvp);                               // 0

    gemm_proj_kernel<<<dim3(LDIM/128, CDIM/128, 24), 256, PJ_SMEM>>>(
        p_Wqp, p_Xqp, bq,
        p_Wkp, p_Xkp, bk,
        p_Wvp, p_Xvp, bv);                                              // 1

    stats_mma_kernel<<<dim3(LDIM/128, NH), 256, ST_SMEM>>>();           // 2
    attnout_mma_kernel<<<dim3(LDIM/128, NH), 256, AO_SMEM>>>(out);      // 3 (profiled)
}